// round 1
// baseline (speedup 1.0000x reference)
#include <cuda_runtime.h>
#include <cstdint>

#define NN 100000
#define DD 64
#define EE 400000
#define TT 5

// Scratch (device globals — no allocation allowed)
__device__ float g_P[(size_t)2 * TT * NN * DD];   // [t*2+half][n][64], 256MB
__device__ int   g_counts[TT * NN];
__device__ float g_inv[TT * NN];
__device__ float g_w[TT];

// ---------------------------------------------------------------- utilities
__device__ __forceinline__ unsigned long long pack2(float a, float b) {
    unsigned long long r;
    asm("mov.b64 %0, {%1, %2};" : "=l"(r) : "f"(a), "f"(b));
    return r;
}
__device__ __forceinline__ void unpack2(unsigned long long v, float& a, float& b) {
    asm("mov.b64 {%0, %1}, %2;" : "=f"(a), "=f"(b) : "l"(v));
}
__device__ __forceinline__ void fma2(unsigned long long& d, unsigned long long a,
                                     unsigned long long b) {
    asm("fma.rn.f32x2 %0, %1, %2, %3;" : "=l"(d) : "l"(a), "l"(b), "l"(d));
}

// ---------------------------------------------------------------- kernels
__global__ void zero_kernel(float* out) {
    int i = blockIdx.x * blockDim.x + threadIdx.x;
    if (i < NN * DD) out[i] = 0.0f;
    if (i < TT * NN) g_counts[i] = 0;
}

__global__ void softmax_kernel(const float* __restrict__ ea) {
    if (threadIdx.x == 0) {
        float m = -1e30f;
        for (int t = 0; t < TT; t++) m = fmaxf(m, ea[t]);
        float e[TT], s = 0.0f;
        for (int t = 0; t < TT; t++) { e[t] = expf(ea[t] - m); s += e[t]; }
        for (int t = 0; t < TT; t++) g_w[t] = e[t] / s;
    }
}

__global__ void count_kernel(const int* __restrict__ edges) {
    int i = blockIdx.x * blockDim.x + threadIdx.x;
    if (i >= TT * EE) return;
    int t = i / EE;
    int e = i - t * EE;
    int src = edges[(size_t)t * 2 * EE + e];
    atomicAdd(&g_counts[t * NN + src], 1);
}

__global__ void inv_kernel() {
    int i = blockIdx.x * blockDim.x + threadIdx.x;
    if (i >= TT * NN) return;
    int c = g_counts[i];
    g_inv[i] = g_w[i / NN] / (float)(c > 1 ? c : 1);
}

// P[y][n][c] = sum_k x[n][k] * W[t][half*64+k][c]   where y = t*2+half
// Block: 128 nodes x 64 cols, 128 threads, each thread 8 nodes x 8 cols.
// Uses packed f32x2 FMA (col pairs), acc[i][j] covers cols (cg*8+2j, +1).
__global__ __launch_bounds__(128) void gemm_kernel(const float* __restrict__ x,
                                                   const float* __restrict__ W) {
    __shared__ float xsT[64 * 128];  // [k][n] transposed
    __shared__ float ws[64 * 64];    // [k][c]
    const int tid = threadIdx.x;
    const int y = blockIdx.y;        // t*2+half, 0..9
    const int n0 = blockIdx.x * 128;

    // Load W slab (rows y*64 .. y*64+63 of the (T*128,64) matrix): 4096 floats
    {
        const float4* Wg = (const float4*)(W + (size_t)y * 4096);
        float4* ws4 = (float4*)ws;
#pragma unroll
        for (int i = 0; i < 8; i++) ws4[tid + i * 128] = Wg[tid + i * 128];
    }
    // Load x rows: thread owns row n0+tid; STS transposed (conflict-free: bank = tid%32)
    {
        const int n = n0 + tid;
        const float4* xg = (const float4*)(x + (size_t)n * 64);
#pragma unroll
        for (int i = 0; i < 16; i++) {
            float4 v = (n < NN) ? xg[i] : make_float4(0.f, 0.f, 0.f, 0.f);
            xsT[(i * 4 + 0) * 128 + tid] = v.x;
            xsT[(i * 4 + 1) * 128 + tid] = v.y;
            xsT[(i * 4 + 2) * 128 + tid] = v.z;
            xsT[(i * 4 + 3) * 128 + tid] = v.w;
        }
    }
    __syncthreads();

    const int cg = tid & 7;    // col group: cols cg*8 .. +7
    const int ng = tid >> 3;   // node group: nodes ng*8 .. +7

    unsigned long long acc[8][4];
#pragma unroll
    for (int i = 0; i < 8; i++)
#pragma unroll
        for (int j = 0; j < 4; j++) acc[i][j] = 0ull;

#pragma unroll 4
    for (int k = 0; k < 64; k++) {
        float4 xa = *(const float4*)&xsT[k * 128 + ng * 8];
        float4 xb = *(const float4*)&xsT[k * 128 + ng * 8 + 4];
        float4 w0 = *(const float4*)&ws[k * 64 + cg * 8];
        float4 w1 = *(const float4*)&ws[k * 64 + cg * 8 + 4];
        unsigned long long wp[4];
        wp[0] = pack2(w0.x, w0.y);
        wp[1] = pack2(w0.z, w0.w);
        wp[2] = pack2(w1.x, w1.y);
        wp[3] = pack2(w1.z, w1.w);
        unsigned long long xp[8];
        xp[0] = pack2(xa.x, xa.x); xp[1] = pack2(xa.y, xa.y);
        xp[2] = pack2(xa.z, xa.z); xp[3] = pack2(xa.w, xa.w);
        xp[4] = pack2(xb.x, xb.x); xp[5] = pack2(xb.y, xb.y);
        xp[6] = pack2(xb.z, xb.z); xp[7] = pack2(xb.w, xb.w);
#pragma unroll
        for (int i = 0; i < 8; i++)
#pragma unroll
            for (int j = 0; j < 4; j++) fma2(acc[i][j], xp[i], wp[j]);
    }

    // Epilogue: write P
#pragma unroll
    for (int i = 0; i < 8; i++) {
        const int n = n0 + ng * 8 + i;
        if (n < NN) {
            float r0, r1, r2, r3, r4, r5, r6, r7;
            unpack2(acc[i][0], r0, r1);
            unpack2(acc[i][1], r2, r3);
            unpack2(acc[i][2], r4, r5);
            unpack2(acc[i][3], r6, r7);
            float4* Pp = (float4*)&g_P[(((size_t)y * NN) + n) * 64 + cg * 8];
            Pp[0] = make_float4(r0, r1, r2, r3);
            Pp[1] = make_float4(r4, r5, r6, r7);
        }
    }
}

// Edge aggregation: 16 lanes (float4 each) per edge-instance.
// out[src] += inv[t][src] * relu(P[t,0][src] + P[t,1][dst] + b[t])
__global__ __launch_bounds__(256) void edge_kernel(const int* __restrict__ edges,
                                                   const float* __restrict__ bvec,
                                                   float* __restrict__ out) {
    int gtid = blockIdx.x * blockDim.x + threadIdx.x;
    int grp = gtid >> 4;
    int lane = gtid & 15;
    if (grp >= TT * EE) return;
    int t = grp / EE;
    int e = grp - t * EE;

    const int* eb = edges + (size_t)t * 2 * EE;
    int src = eb[e];
    int dst = eb[EE + e];

    float s = g_inv[t * NN + src];
    const float4* P4 = (const float4*)g_P;
    float4 a = P4[((size_t)(2 * t) * NN + src) * 16 + lane];
    float4 c = P4[((size_t)(2 * t + 1) * NN + dst) * 16 + lane];
    float4 bi = ((const float4*)bvec)[t * 16 + lane];

    float4 v;
    v.x = fmaxf(a.x + c.x + bi.x, 0.0f) * s;
    v.y = fmaxf(a.y + c.y + bi.y, 0.0f) * s;
    v.z = fmaxf(a.z + c.z + bi.z, 0.0f) * s;
    v.w = fmaxf(a.w + c.w + bi.w, 0.0f) * s;

    float* dp = out + ((size_t)src * 64 + lane * 4);
    asm volatile("red.global.add.v4.f32 [%0], {%1, %2, %3, %4};"
                 :: "l"(dp), "f"(v.x), "f"(v.y), "f"(v.z), "f"(v.w)
                 : "memory");
}

// ---------------------------------------------------------------- launcher
extern "C" void kernel_launch(void* const* d_in, const int* in_sizes, int n_in,
                              void* d_out, int out_size) {
    const float* x = nullptr;
    const float* W = nullptr;
    const float* b = nullptr;
    const float* ea = nullptr;
    const int* edges = nullptr;

    for (int i = 0; i < n_in; i++) {
        switch (in_sizes[i]) {
            case NN * DD:          x     = (const float*)d_in[i]; break;  // 6,400,000
            case TT * 2 * DD * DD: W     = (const float*)d_in[i]; break;  // 40,960
            case TT * DD:          b     = (const float*)d_in[i]; break;  // 320
            case TT:               ea    = (const float*)d_in[i]; break;  // 5
            case TT * 2 * EE:      edges = (const int*)d_in[i];   break;  // 4,000,000
        }
    }

    float* out = (float*)d_out;

    zero_kernel<<<(NN * DD + 255) / 256, 256>>>(out);
    softmax_kernel<<<1, 32>>>(ea);
    count_kernel<<<(TT * EE + 255) / 256, 256>>>(edges);
    inv_kernel<<<(TT * NN + 255) / 256, 256>>>();
    gemm_kernel<<<dim3((NN + 127) / 128, 2 * TT), 128>>>(x, W);
    edge_kernel<<<(TT * EE * 16) / 256, 256>>>(edges, b, out);
}

// round 2
// speedup vs baseline: 1.0503x; 1.0503x over previous
#include <cuda_runtime.h>
#include <cuda_fp16.h>
#include <cstdint>

#define NN 100000
#define DD 64
#define EE 400000
#define TT 5

// Scratch (device globals — no allocation allowed)
__device__ __half g_Ph[(size_t)2 * TT * NN * DD];  // fp16 tables, 128MB
__device__ int   g_counts[TT * NN];
__device__ float g_inv[TT * NN];
__device__ float g_w[TT];

// ---------------------------------------------------------------- utilities
__device__ __forceinline__ unsigned long long pack2(float a, float b) {
    unsigned long long r;
    asm("mov.b64 %0, {%1, %2};" : "=l"(r) : "f"(a), "f"(b));
    return r;
}
__device__ __forceinline__ void unpack2(unsigned long long v, float& a, float& b) {
    asm("mov.b64 {%0, %1}, %2;" : "=f"(a), "=f"(b) : "l"(v));
}
__device__ __forceinline__ void fma2(unsigned long long& d, unsigned long long a,
                                     unsigned long long b) {
    asm("fma.rn.f32x2 %0, %1, %2, %3;" : "=l"(d) : "l"(a), "l"(b), "l"(d));
}

// ---------------------------------------------------------------- kernels
__global__ void zero_kernel(float* out) {
    int i = blockIdx.x * blockDim.x + threadIdx.x;
    if (i < NN * DD) out[i] = 0.0f;
    if (i < TT * NN) g_counts[i] = 0;
}

__global__ void softmax_kernel(const float* __restrict__ ea) {
    if (threadIdx.x == 0) {
        float m = -1e30f;
        for (int t = 0; t < TT; t++) m = fmaxf(m, ea[t]);
        float e[TT], s = 0.0f;
        for (int t = 0; t < TT; t++) { e[t] = expf(ea[t] - m); s += e[t]; }
        for (int t = 0; t < TT; t++) g_w[t] = e[t] / s;
    }
}

__global__ void count_kernel(const int* __restrict__ edges) {
    int i = blockIdx.x * blockDim.x + threadIdx.x;
    if (i >= TT * EE) return;
    int t = i / EE;
    int e = i - t * EE;
    int src = edges[(size_t)t * 2 * EE + e];
    atomicAdd(&g_counts[t * NN + src], 1);
}

__global__ void inv_kernel() {
    int i = blockIdx.x * blockDim.x + threadIdx.x;
    if (i >= TT * NN) return;
    int c = g_counts[i];
    g_inv[i] = g_w[i / NN] / (float)(c > 1 ? c : 1);
}

// P[y][n][c] = sum_k x[n][k] * W[t][half*64+k][c]   where y = t*2+half.
// Bias b[t] folded into the src half (y even). Output stored fp16.
// Block: 128 nodes x 64 cols, 128 threads, each thread 8 nodes x 8 cols.
__global__ __launch_bounds__(128) void gemm_kernel(const float* __restrict__ x,
                                                   const float* __restrict__ W,
                                                   const float* __restrict__ bvec) {
    __shared__ float xsT[64 * 128];  // [k][n] transposed
    __shared__ float ws[64 * 64];    // [k][c]
    const int tid = threadIdx.x;
    const int y = blockIdx.y;        // t*2+half, 0..9
    const int n0 = blockIdx.x * 128;

    // Load W slab (rows y*64 .. y*64+63 of the (T*128,64) matrix): 4096 floats
    {
        const float4* Wg = (const float4*)(W + (size_t)y * 4096);
        float4* ws4 = (float4*)ws;
#pragma unroll
        for (int i = 0; i < 8; i++) ws4[tid + i * 128] = Wg[tid + i * 128];
    }
    // Load x rows: thread owns row n0+tid; STS transposed (conflict-free)
    {
        const int n = n0 + tid;
        const float4* xg = (const float4*)(x + (size_t)n * 64);
#pragma unroll
        for (int i = 0; i < 16; i++) {
            float4 v = (n < NN) ? xg[i] : make_float4(0.f, 0.f, 0.f, 0.f);
            xsT[(i * 4 + 0) * 128 + tid] = v.x;
            xsT[(i * 4 + 1) * 128 + tid] = v.y;
            xsT[(i * 4 + 2) * 128 + tid] = v.z;
            xsT[(i * 4 + 3) * 128 + tid] = v.w;
        }
    }
    __syncthreads();

    const int cg = tid & 7;    // col group: cols cg*8 .. +7
    const int ng = tid >> 3;   // node group: nodes ng*8 .. +7

    unsigned long long acc[8][4];
#pragma unroll
    for (int i = 0; i < 8; i++)
#pragma unroll
        for (int j = 0; j < 4; j++) acc[i][j] = 0ull;

#pragma unroll 4
    for (int k = 0; k < 64; k++) {
        float4 xa = *(const float4*)&xsT[k * 128 + ng * 8];
        float4 xb = *(const float4*)&xsT[k * 128 + ng * 8 + 4];
        // W pairs read directly as packed u64 (cols are naturally adjacent)
        const ulonglong2* wp01 = (const ulonglong2*)&ws[k * 64 + cg * 8];
        ulonglong2 wA = wp01[0];
        ulonglong2 wB = wp01[1];
        unsigned long long wp[4] = {wA.x, wA.y, wB.x, wB.y};
        unsigned long long xp[8];
        xp[0] = pack2(xa.x, xa.x); xp[1] = pack2(xa.y, xa.y);
        xp[2] = pack2(xa.z, xa.z); xp[3] = pack2(xa.w, xa.w);
        xp[4] = pack2(xb.x, xb.x); xp[5] = pack2(xb.y, xb.y);
        xp[6] = pack2(xb.z, xb.z); xp[7] = pack2(xb.w, xb.w);
#pragma unroll
        for (int i = 0; i < 8; i++)
#pragma unroll
            for (int j = 0; j < 4; j++) fma2(acc[i][j], xp[i], wp[j]);
    }

    // Bias (src half only): per-column values for this thread's 8 cols
    float bv[8];
    if ((y & 1) == 0) {
        const int t = y >> 1;
#pragma unroll
        for (int j = 0; j < 8; j++) bv[j] = bvec[t * DD + cg * 8 + j];
    } else {
#pragma unroll
        for (int j = 0; j < 8; j++) bv[j] = 0.0f;
    }

    // Epilogue: convert to fp16 and write P
#pragma unroll
    for (int i = 0; i < 8; i++) {
        const int n = n0 + ng * 8 + i;
        if (n < NN) {
            float r[8];
            unpack2(acc[i][0], r[0], r[1]);
            unpack2(acc[i][1], r[2], r[3]);
            unpack2(acc[i][2], r[4], r[5]);
            unpack2(acc[i][3], r[6], r[7]);
            __half2 h[4];
#pragma unroll
            for (int j = 0; j < 4; j++)
                h[j] = __floats2half2_rn(r[2 * j] + bv[2 * j], r[2 * j + 1] + bv[2 * j + 1]);
            uint4* Pp = (uint4*)&g_Ph[(((size_t)y * NN) + n) * 64 + cg * 8];
            uint4 pk;
            pk.x = *(unsigned*)&h[0];
            pk.y = *(unsigned*)&h[1];
            pk.z = *(unsigned*)&h[2];
            pk.w = *(unsigned*)&h[3];
            *Pp = pk;
        }
    }
}

// Edge aggregation: 8 lanes (8 fp16 cols = 16B each) per edge-instance.
// out[src] += inv[t][src] * relu(A'[t][src] + C[t][dst])   (bias pre-folded)
__global__ __launch_bounds__(256) void edge_kernel(const int* __restrict__ edges,
                                                   float* __restrict__ out) {
    int gtid = blockIdx.x * blockDim.x + threadIdx.x;
    int grp = gtid >> 3;
    int lane = gtid & 7;
    if (grp >= TT * EE) return;
    int t = grp / EE;
    int e = grp - t * EE;

    const int* eb = edges + (size_t)t * 2 * EE;
    int src = eb[e];
    int dst = eb[EE + e];

    float s = g_inv[t * NN + src];
    const uint4* P4 = (const uint4*)g_Ph;   // 8 uint4 per 64-col row
    uint4 av = P4[((size_t)(2 * t) * NN + src) * 8 + lane];
    uint4 cv = P4[((size_t)(2 * t + 1) * NN + dst) * 8 + lane];

    float v[8];
    {
        const __half2* ah = (const __half2*)&av;
        const __half2* ch = (const __half2*)&cv;
#pragma unroll
        for (int j = 0; j < 4; j++) {
            float2 fa = __half22float2(ah[j]);
            float2 fc = __half22float2(ch[j]);
            v[2 * j]     = fmaxf(fa.x + fc.x, 0.0f) * s;
            v[2 * j + 1] = fmaxf(fa.y + fc.y, 0.0f) * s;
        }
    }

    float* dp = out + ((size_t)src * 64 + lane * 8);
    asm volatile("red.global.add.v4.f32 [%0], {%1, %2, %3, %4};"
                 :: "l"(dp), "f"(v[0]), "f"(v[1]), "f"(v[2]), "f"(v[3])
                 : "memory");
    asm volatile("red.global.add.v4.f32 [%0], {%1, %2, %3, %4};"
                 :: "l"(dp + 4), "f"(v[4]), "f"(v[5]), "f"(v[6]), "f"(v[7])
                 : "memory");
}

// ---------------------------------------------------------------- launcher
extern "C" void kernel_launch(void* const* d_in, const int* in_sizes, int n_in,
                              void* d_out, int out_size) {
    const float* x = nullptr;
    const float* W = nullptr;
    const float* b = nullptr;
    const float* ea = nullptr;
    const int* edges = nullptr;

    for (int i = 0; i < n_in; i++) {
        switch (in_sizes[i]) {
            case NN * DD:          x     = (const float*)d_in[i]; break;  // 6,400,000
            case TT * 2 * DD * DD: W     = (const float*)d_in[i]; break;  // 40,960
            case TT * DD:          b     = (const float*)d_in[i]; break;  // 320
            case TT:               ea    = (const float*)d_in[i]; break;  // 5
            case TT * 2 * EE:      edges = (const int*)d_in[i];   break;  // 4,000,000
        }
    }

    float* out = (float*)d_out;

    // Order chosen so the ncu -s window lands on gemm_kernel (position of
    // inv_kernel last round).
    zero_kernel<<<(NN * DD + 255) / 256, 256>>>(out);
    softmax_kernel<<<1, 32>>>(ea);
    count_kernel<<<(TT * EE + 255) / 256, 256>>>(edges);
    gemm_kernel<<<dim3((NN + 127) / 128, 2 * TT), 128>>>(x, W, b);
    inv_kernel<<<(TT * NN + 255) / 256, 256>>>();
    edge_kernel<<<(TT * EE * 8 + 255) / 256, 256>>>(edges, out);
}